// round 1
// baseline (speedup 1.0000x reference)
#include <cuda_runtime.h>

#define LDIM 768
#define LL   (768*768)
#define FDIM 128
#define PDIM 32

// Scratch (device globals; allocation-free rule)
__device__ float g_Wt[FDIM*192];                 // packed [k][j] j: 0-31 aW, 32-63 agW, 64-191 gW
__device__ float g_proj[(size_t)PDIM*LL];        // channel-major [c][i][l]
__device__ float g_pair[(size_t)PDIM*LL];        // channel-major [c][i][j]
__device__ float g_gate[(size_t)LL*FDIM];        // [i*L+j][f]

__device__ __forceinline__ float sigmoidf_(float x) { return 1.0f/(1.0f + __expf(-x)); }

// ---------------------------------------------------------------------------
// Kernel 0: pack/transpose weights into [k][192]
// ---------------------------------------------------------------------------
__global__ void k_pack(const float* __restrict__ aW, const float* __restrict__ agW,
                       const float* __restrict__ gW)
{
    int idx = blockIdx.x * 256 + threadIdx.x;     // 0 .. 128*192-1
    if (idx < FDIM*192) {
        int k = idx / 192, j = idx % 192;
        float v;
        if (j < 32)      v = aW[j*FDIM + k];
        else if (j < 64) v = agW[(j-32)*FDIM + k];
        else             v = gW[(j-64)*FDIM + k];
        g_Wt[idx] = v;
    }
}

// ---------------------------------------------------------------------------
// Kernel 1: layernorm(F) + [a, ag, gate] projections, fused.
// Block = 64 positions; 256 threads; GEMM 64x192x128 with register tiling.
// Outputs: g_proj (channel-major), g_gate.
// ---------------------------------------------------------------------------
__global__ __launch_bounds__(256) void k_ln_proj_gate(
    const float* __restrict__ feat,
    const float* __restrict__ nw, const float* __restrict__ nb,
    const float* __restrict__ ab, const float* __restrict__ agb,
    const float* __restrict__ gb)
{
    __shared__ float sx[64*128];     // normalized x, [p][k]    32 KB
    __shared__ float sw[16*192];     // weight k-chunk [k][j]   12 KB

    int t  = threadIdx.x;
    int tx = t & 31, ty = t >> 5;
    int base = blockIdx.x * 64;

    // ---- Phase 1: layernorm, one warp handles 8 positions ----
    const float4* nw4 = (const float4*)nw;
    const float4* nb4 = (const float4*)nb;
    float4 w4 = nw4[tx], b4 = nb4[tx];
    for (int s = 0; s < 8; s++) {
        int p = ty*8 + s;
        float4 v = ((const float4*)(feat + (size_t)(base+p)*FDIM))[tx];
        float sum = v.x+v.y+v.z+v.w;
        float sq  = v.x*v.x + v.y*v.y + v.z*v.z + v.w*v.w;
        #pragma unroll
        for (int o = 16; o > 0; o >>= 1) {
            sum += __shfl_xor_sync(0xffffffffu, sum, o);
            sq  += __shfl_xor_sync(0xffffffffu, sq,  o);
        }
        float mu   = sum * (1.0f/128.0f);
        float var  = sq  * (1.0f/128.0f) - mu*mu;
        float rstd = rsqrtf(var + 1e-5f);
        float4 xh;
        xh.x = (v.x-mu)*rstd*w4.x + b4.x;
        xh.y = (v.y-mu)*rstd*w4.y + b4.y;
        xh.z = (v.z-mu)*rstd*w4.z + b4.z;
        xh.w = (v.w-mu)*rstd*w4.w + b4.w;
        ((float4*)(sx + p*128))[tx] = xh;
    }
    __syncthreads();

    // ---- Phase 2: X[64x128] @ Wcat[128x192]; thread = 8 pos x 6 channels ----
    float acc[8][6];
    #pragma unroll
    for (int r = 0; r < 8; r++)
        #pragma unroll
        for (int cc = 0; cc < 6; cc++) acc[r][cc] = 0.0f;

    for (int kc = 0; kc < 8; kc++) {
        #pragma unroll
        for (int e = 0; e < 12; e++) {
            int idx = t + e*256;                  // 3072 floats
            sw[idx] = g_Wt[kc*3072 + idx];
        }
        __syncthreads();
        #pragma unroll 4
        for (int k = 0; k < 16; k++) {
            float xv[8];
            #pragma unroll
            for (int r = 0; r < 8; r++) xv[r] = sx[(ty*8+r)*128 + kc*16 + k];  // broadcast
            float wv[6];
            #pragma unroll
            for (int cc = 0; cc < 6; cc++) wv[cc] = sw[k*192 + tx + 32*cc];    // conflict-free
            #pragma unroll
            for (int r = 0; r < 8; r++)
                #pragma unroll
                for (int cc = 0; cc < 6; cc++)
                    acc[r][cc] += xv[r] * wv[cc];
        }
        __syncthreads();
    }

    // ---- Epilogue ----
    float abv  = ab[tx];
    float agbv = agb[tx];
    float gbv0 = gb[tx], gbv1 = gb[tx+32], gbv2 = gb[tx+64], gbv3 = gb[tx+96];

    float projv[8];
    #pragma unroll
    for (int r = 0; r < 8; r++) {
        int p = ty*8 + r;
        projv[r] = (acc[r][0] + abv) * sigmoidf_(acc[r][1] + agbv);
        size_t go = (size_t)(base + p)*FDIM + tx;
        g_gate[go      ] = sigmoidf_(acc[r][2] + gbv0);
        g_gate[go + 32 ] = sigmoidf_(acc[r][3] + gbv1);
        g_gate[go + 64 ] = sigmoidf_(acc[r][4] + gbv2);
        g_gate[go + 96 ] = sigmoidf_(acc[r][5] + gbv3);
    }
    __syncthreads();
    // stage proj in smem as [c][p] then write coalesced, channel-major
    #pragma unroll
    for (int r = 0; r < 8; r++) sx[tx*64 + ty*8 + r] = projv[r];
    __syncthreads();
    for (int idx = t; idx < 2048; idx += 256) {
        int c = idx >> 6, p = idx & 63;
        g_proj[(size_t)c*LL + base + p] = sx[idx];
    }
}

// ---------------------------------------------------------------------------
// Kernel 2: pair[i,j,c] = sum_l proj[c][i][l]*proj[c][j][l]  (symmetric: C=A A^T)
// Upper-triangle tiles only; mirror-write for off-diagonal tiles.
// 64x64 tile, TK=32, 256 threads, 4x4 micro-tile.
// ---------------------------------------------------------------------------
__global__ __launch_bounds__(256) void k_einsum()
{
    __shared__ float As[64][33];
    __shared__ float Bs[64][33];

    int t  = threadIdx.x;
    int tx = t & 15, ty = t >> 4;
    int ch = blockIdx.y;

    // map linear upper-triangle tile index -> (bi, bj), n = 12
    int tt = blockIdx.x, bi = 0;
    while (tt >= 12 - bi) { tt -= 12 - bi; bi++; }
    int bj = bi + tt;

    const float* A = g_proj + (size_t)ch * LL;
    int i0 = bi*64, j0 = bj*64;

    float c[4][4];
    #pragma unroll
    for (int r = 0; r < 4; r++)
        #pragma unroll
        for (int s = 0; s < 4; s++) c[r][s] = 0.0f;

    for (int k0 = 0; k0 < LDIM; k0 += 32) {
        #pragma unroll
        for (int e = 0; e < 8; e++) {
            int idx = t + e*256;
            int row = idx >> 5, kk = idx & 31;
            As[row][kk] = A[(size_t)(i0+row)*LDIM + k0 + kk];
            Bs[row][kk] = A[(size_t)(j0+row)*LDIM + k0 + kk];
        }
        __syncthreads();
        #pragma unroll 8
        for (int k = 0; k < 32; k++) {
            float a[4], b[4];
            #pragma unroll
            for (int r = 0; r < 4; r++) a[r] = As[ty*4+r][k];
            #pragma unroll
            for (int s = 0; s < 4; s++) b[s] = Bs[tx*4+s][k];
            #pragma unroll
            for (int r = 0; r < 4; r++)
                #pragma unroll
                for (int s = 0; s < 4; s++)
                    c[r][s] += a[r]*b[s];
        }
        __syncthreads();
    }

    float* Cc = g_pair + (size_t)ch * LL;
    #pragma unroll
    for (int r = 0; r < 4; r++) {
        int ic = i0 + ty*4 + r;
        float4 v = make_float4(c[r][0], c[r][1], c[r][2], c[r][3]);
        *((float4*)(Cc + (size_t)ic*LDIM + j0 + tx*4)) = v;
    }
    if (bi != bj) {
        #pragma unroll
        for (int s = 0; s < 4; s++) {
            int jc = j0 + tx*4 + s;
            #pragma unroll
            for (int r = 0; r < 4; r++)
                Cc[(size_t)jc*LDIM + i0 + ty*4 + r] = c[r][s];
        }
    }
}

// ---------------------------------------------------------------------------
// Kernel 3: out = (layernorm_P(pair) @ oW^T + ob) * gate
// Block = (i fixed, 64 consecutive j); 256 threads.
// ---------------------------------------------------------------------------
__global__ __launch_bounds__(256) void k_out(
    const float* __restrict__ onw, const float* __restrict__ onb,
    const float* __restrict__ oW, const float* __restrict__ ob,
    float* __restrict__ out)
{
    __shared__ float sp[32][64];     // pair values [c][jj], 8 KB

    int t  = threadIdx.x;
    int i  = blockIdx.y;
    int j0 = blockIdx.x * 64;
    size_t posbase = (size_t)i*LDIM + j0;

    for (int idx = t; idx < 2048; idx += 256) {
        int cc = idx >> 6, jj = idx & 63;
        sp[cc][jj] = g_pair[(size_t)cc*LL + posbase + jj];
    }
    __syncthreads();

    // layernorm over P=32 (threads 0..63, one position each)
    if (t < 64) {
        float y[32];
        float sum = 0.0f, sq = 0.0f;
        #pragma unroll
        for (int cc = 0; cc < 32; cc++) {
            y[cc] = sp[cc][t];
            sum += y[cc];
            sq  += y[cc]*y[cc];
        }
        float mu   = sum * (1.0f/32.0f);
        float var  = sq  * (1.0f/32.0f) - mu*mu;
        float rstd = rsqrtf(var + 1e-5f);
        #pragma unroll
        for (int cc = 0; cc < 32; cc++)
            sp[cc][t] = (y[cc]-mu)*rstd*onw[cc] + onb[cc];
    }
    __syncthreads();

    // out[pos][f] = sum_c yn[pos][c]*oW[f][c] + ob[f], then * gate
    int f = t & 127, jgrp = t >> 7;
    float wreg[32];
    const float4* ow4 = (const float4*)(oW + f*32);
    #pragma unroll
    for (int q = 0; q < 8; q++) {
        float4 v = ow4[q];
        wreg[q*4+0] = v.x; wreg[q*4+1] = v.y; wreg[q*4+2] = v.z; wreg[q*4+3] = v.w;
    }
    float obv = ob[f];

    for (int jb = 0; jb < 8; jb++) {
        int jj0 = jgrp*32 + jb*4;
        float a0 = obv, a1 = obv, a2 = obv, a3 = obv;
        #pragma unroll
        for (int cc = 0; cc < 32; cc++) {
            float4 y = *((const float4*)&sp[cc][jj0]);
            a0 += y.x*wreg[cc];
            a1 += y.y*wreg[cc];
            a2 += y.z*wreg[cc];
            a3 += y.w*wreg[cc];
        }
        size_t o = (posbase + jj0)*FDIM + f;
        a0 *= g_gate[o        ];
        a1 *= g_gate[o + 128  ];
        a2 *= g_gate[o + 256  ];
        a3 *= g_gate[o + 384  ];
        out[o        ] = a0;
        out[o + 128  ] = a1;
        out[o + 256  ] = a2;
        out[o + 384  ] = a3;
    }
}

// ---------------------------------------------------------------------------
extern "C" void kernel_launch(void* const* d_in, const int* in_sizes, int n_in,
                              void* d_out, int out_size)
{
    const float* feat = (const float*)d_in[0];
    const float* nw   = (const float*)d_in[1];
    const float* nb   = (const float*)d_in[2];
    const float* onw  = (const float*)d_in[3];
    const float* onb  = (const float*)d_in[4];
    const float* aW   = (const float*)d_in[5];
    const float* ab   = (const float*)d_in[6];
    const float* agW  = (const float*)d_in[7];
    const float* agb  = (const float*)d_in[8];
    const float* oW   = (const float*)d_in[9];
    const float* ob   = (const float*)d_in[10];
    const float* gW   = (const float*)d_in[11];
    const float* gb   = (const float*)d_in[12];
    float* out = (float*)d_out;

    k_pack<<<96, 256>>>(aW, agW, gW);
    k_ln_proj_gate<<<LL/64, 256>>>(feat, nw, nb, ab, agb, gb);
    k_einsum<<<dim3(78, 32), 256>>>();
    k_out<<<dim3(12, 768), 256>>>(onw, onb, oW, ob, out);
}

// round 3
// speedup vs baseline: 1.4205x; 1.4205x over previous
#include <cuda_runtime.h>
#include <cuda_bf16.h>
#include <cuda_fp16.h>
#include <cstdint>

#define LDIM 768
#define LL   (768*768)
#define FDIM 128
#define PDIM 32

// ---------------- device scratch (allocation-free rule) ----------------
__device__ __nv_bfloat16 g_Wbh[192*128];            // reordered weights hi [n][k]
__device__ __nv_bfloat16 g_Wbl[192*128];            // reordered weights lo [n][k]
__device__ __nv_bfloat16 g_projh[(size_t)PDIM*LL];  // proj hi, channel-major [c][pos]
__device__ __nv_bfloat16 g_projl[(size_t)PDIM*LL];  // proj lo
__device__ float         g_pair[(size_t)PDIM*LL];   // pair, channel-major [c][i*L+j]
__device__ __half        g_gate16[(size_t)LL*FDIM]; // gate fp16 [pos][f]

__device__ __forceinline__ float sigmoidf_(float x) { return 1.0f/(1.0f + __expf(-x)); }

__device__ __forceinline__ void ldsm4(uint32_t (&r)[4], uint32_t addr) {
    asm volatile("ldmatrix.sync.aligned.m8n8.x4.shared.b16 {%0,%1,%2,%3}, [%4];"
        : "=r"(r[0]), "=r"(r[1]), "=r"(r[2]), "=r"(r[3]) : "r"(addr));
}
__device__ __forceinline__ void mma_bf16(float (&c)[4], const uint32_t (&a)[4],
                                         uint32_t b0, uint32_t b1) {
    asm volatile("mma.sync.aligned.m16n8k16.row.col.f32.bf16.bf16.f32 "
        "{%0,%1,%2,%3},{%4,%5,%6,%7},{%8,%9},{%0,%1,%2,%3};"
        : "+f"(c[0]), "+f"(c[1]), "+f"(c[2]), "+f"(c[3])
        : "r"(a[0]), "r"(a[1]), "r"(a[2]), "r"(a[3]), "r"(b0), "r"(b1));
}
__device__ __forceinline__ uint32_t smaddr(const void* p) {
    return (uint32_t)__cvta_generic_to_shared(p);
}

// ---------------------------------------------------------------------------
// Kernel 0: pack weights -> bf16 hi/lo planes, [n][k] layout.
// n reorder: n<64: even n = aW[n/2], odd n = agW[n/2]; n>=64: gW[n-64].
// ---------------------------------------------------------------------------
__global__ void k_pack(const float* __restrict__ aW, const float* __restrict__ agW,
                       const float* __restrict__ gW)
{
    int idx = blockIdx.x * 256 + threadIdx.x;  // 0 .. 192*128-1
    if (idx >= 192*128) return;
    int n = idx >> 7, k = idx & 127;
    float v;
    if (n < 64) { int ch = n >> 1; v = (n & 1) ? agW[ch*FDIM + k] : aW[ch*FDIM + k]; }
    else        { v = gW[(n-64)*FDIM + k]; }
    __nv_bfloat16 vh = __float2bfloat16(v);
    __nv_bfloat16 vl = __float2bfloat16(v - __bfloat162float(vh));
    g_Wbh[idx] = vh;
    g_Wbl[idx] = vl;
}

// ---------------------------------------------------------------------------
// Kernel 1: LN(F) + X[128,128] @ Wcat[128,192] via bf16x3 tensor MMA.
// Block = 128 positions, 256 threads (8 warps: 2M x 4N; warp = 64 rows x 48 cols).
// smem: XH/XL [128][136] bf16, WH/WL [192][136] bf16 (full K resident).
// Epilogue: proj -> bf16 hi/lo channel-major; gate -> fp16.
// ---------------------------------------------------------------------------
#define X_STRIDE 136
#define K1_SMEM  174080

__global__ __launch_bounds__(256) void k1_ln_proj_gate(
    const float* __restrict__ feat,
    const float* __restrict__ nw, const float* __restrict__ nb,
    const float* __restrict__ ab, const float* __restrict__ agb,
    const float* __restrict__ gb)
{
    extern __shared__ char sm[];
    __nv_bfloat16* XH = (__nv_bfloat16*)sm;                 // 128*136*2 = 34816
    __nv_bfloat16* XL = (__nv_bfloat16*)(sm + 34816);
    __nv_bfloat16* WH = (__nv_bfloat16*)(sm + 69632);       // 192*136*2 = 52224
    __nv_bfloat16* WL = (__nv_bfloat16*)(sm + 121856);
    // staging (aliases X region, used after mma + sync)
    __half*        SGATE = (__half*)sm;                     // [128][128] fp16 = 32768
    __nv_bfloat16* SPH   = (__nv_bfloat16*)(sm + 32768);    // [32][128]  = 8192
    __nv_bfloat16* SPL   = (__nv_bfloat16*)(sm + 40960);

    int t = threadIdx.x, lane = t & 31, wid = t >> 5;
    int base = blockIdx.x * 128;

    // ---- load W (hi/lo) into smem ----
    for (int i = t; i < 192*16; i += 256) {
        int n = i >> 4, q = i & 15;
        ((float4*)(WH + n*X_STRIDE))[q] = ((const float4*)(g_Wbh + n*128))[q];
        ((float4*)(WL + n*X_STRIDE))[q] = ((const float4*)(g_Wbl + n*128))[q];
    }

    // ---- layernorm: one warp per row-iteration ----
    {
        float4 w4 = ((const float4*)nw)[lane];
        float4 b4 = ((const float4*)nb)[lane];
        for (int rr = 0; rr < 16; rr++) {
            int row = wid*16 + rr;
            float4 v = ((const float4*)(feat + (size_t)(base+row)*FDIM))[lane];
            float sum = v.x+v.y+v.z+v.w;
            float sq  = v.x*v.x + v.y*v.y + v.z*v.z + v.w*v.w;
            #pragma unroll
            for (int o = 16; o > 0; o >>= 1) {
                sum += __shfl_xor_sync(0xffffffffu, sum, o);
                sq  += __shfl_xor_sync(0xffffffffu, sq,  o);
            }
            float mu   = sum * (1.0f/128.0f);
            float var  = sq  * (1.0f/128.0f) - mu*mu;
            float rstd = rsqrtf(var + 1e-5f);
            float x0 = (v.x-mu)*rstd*w4.x + b4.x;
            float x1 = (v.y-mu)*rstd*w4.y + b4.y;
            float x2 = (v.z-mu)*rstd*w4.z + b4.z;
            float x3 = (v.w-mu)*rstd*w4.w + b4.w;
            __nv_bfloat16 h0=__float2bfloat16(x0), h1=__float2bfloat16(x1),
                          h2=__float2bfloat16(x2), h3=__float2bfloat16(x3);
            __nv_bfloat16 l0=__float2bfloat16(x0-__bfloat162float(h0)),
                          l1=__float2bfloat16(x1-__bfloat162float(h1)),
                          l2=__float2bfloat16(x2-__bfloat162float(h2)),
                          l3=__float2bfloat16(x3-__bfloat162float(h3));
            __nv_bfloat162 hh0 = {h0,h1}, hh1 = {h2,h3};
            __nv_bfloat162 ll0 = {l0,l1}, ll1 = {l2,l3};
            uint2 hp, lp;
            hp.x = *(uint32_t*)&hh0; hp.y = *(uint32_t*)&hh1;
            lp.x = *(uint32_t*)&ll0; lp.y = *(uint32_t*)&ll1;
            *(uint2*)(XH + row*X_STRIDE + lane*4) = hp;
            *(uint2*)(XL + row*X_STRIDE + lane*4) = lp;
        }
    }
    __syncthreads();

    // ---- MMA mainloop ----
    int warpM = wid >> 2;        // 0..1 : rows 64*warpM
    int warpN = wid & 3;         // 0..3 : cols 48*warpN
    float c[24][4];
    #pragma unroll
    for (int i = 0; i < 24; i++) { c[i][0]=0.f; c[i][1]=0.f; c[i][2]=0.f; c[i][3]=0.f; }

    int grp = lane >> 3, lr = lane & 7;
    int a_row = (grp & 1)*8 + lr, a_k = (grp >> 1)*8;
    int b_row = (grp >> 1)*8 + lr, b_k = (grp & 1)*8;

    uint32_t xh_b = smaddr(XH), xl_b = smaddr(XL);
    uint32_t wh_b = smaddr(WH), wl_b = smaddr(WL);

    for (int kb = 0; kb < 8; kb++) {
        uint32_t ah[4][4], al[4][4], bh[3][4], bl[3][4];
        #pragma unroll
        for (int mt = 0; mt < 4; mt++) {
            uint32_t off = (uint32_t)(((warpM*64 + mt*16 + a_row)*X_STRIDE + kb*16 + a_k)*2);
            ldsm4(ah[mt], xh_b + off);
            ldsm4(al[mt], xl_b + off);
        }
        #pragma unroll
        for (int np = 0; np < 3; np++) {
            uint32_t off = (uint32_t)(((warpN*48 + np*16 + b_row)*X_STRIDE + kb*16 + b_k)*2);
            ldsm4(bh[np], wh_b + off);
            ldsm4(bl[np], wl_b + off);
        }
        #pragma unroll
        for (int mt = 0; mt < 4; mt++)
            #pragma unroll
            for (int nt = 0; nt < 6; nt++) {
                int np = nt >> 1, h = (nt & 1)*2;
                mma_bf16(c[mt*6+nt], ah[mt], bh[np][h], bh[np][h+1]);  // hi*hi
                mma_bf16(c[mt*6+nt], ah[mt], bl[np][h], bl[np][h+1]);  // hi*lo
                mma_bf16(c[mt*6+nt], al[mt], bh[np][h], bh[np][h+1]);  // lo*hi
            }
    }
    __syncthreads();   // X/W smem now dead; staging region safe

    // ---- epilogue ----
    int r0b = warpM*64 + (lane >> 2);
    int cq  = lane & 3;
    #pragma unroll
    for (int mt = 0; mt < 4; mt++) {
        int r0 = r0b + mt*16, r1 = r0 + 8;
        #pragma unroll
        for (int nt = 0; nt < 6; nt++) {
            int nb_ = warpN*48 + nt*8;
            float v0 = c[mt*6+nt][0], v1 = c[mt*6+nt][1];
            float v2 = c[mt*6+nt][2], v3 = c[mt*6+nt][3];
            if (nb_ < 64) {
                int ch = (nb_ >> 1) + cq;
                float abv = ab[ch], agbv = agb[ch];
                float p0 = (v0 + abv) * sigmoidf_(v1 + agbv);
                float p1 = (v2 + abv) * sigmoidf_(v3 + agbv);
                __nv_bfloat16 h0 = __float2bfloat16(p0);
                __nv_bfloat16 h1 = __float2bfloat16(p1);
                SPH[ch*128 + r0] = h0;
                SPH[ch*128 + r1] = h1;
                SPL[ch*128 + r0] = __float2bfloat16(p0 - __bfloat162float(h0));
                SPL[ch*128 + r1] = __float2bfloat16(p1 - __bfloat162float(h1));
            } else {
                int f = nb_ - 64 + 2*cq;
                float g0 = sigmoidf_(v0 + gb[f]);
                float g1 = sigmoidf_(v1 + gb[f+1]);
                float g2 = sigmoidf_(v2 + gb[f]);
                float g3 = sigmoidf_(v3 + gb[f+1]);
                __half2 ga = __floats2half2_rn(g0, g1);
                __half2 gc = __floats2half2_rn(g2, g3);
                *(__half2*)(SGATE + r0*128 + f) = ga;
                *(__half2*)(SGATE + r1*128 + f) = gc;
            }
        }
    }
    __syncthreads();

    // flush gate (32KB) and proj (2x8KB) coalesced
    {
        const float4* sg = (const float4*)SGATE;
        float4* dg = (float4*)(g_gate16 + (size_t)base*FDIM);
        for (int i = t; i < 2048; i += 256) dg[i] = sg[i];
        const float4* sph = (const float4*)SPH;
        const float4* spl = (const float4*)SPL;
        for (int i = t; i < 512; i += 256) {
            int ch = i >> 4, q = i & 15;      // 16 float4 (=128 bf16) per channel row
            ((float4*)(g_projh + (size_t)ch*LL + base))[q] = sph[i];
            ((float4*)(g_projl + (size_t)ch*LL + base))[q] = spl[i];
        }
    }
}

// ---------------------------------------------------------------------------
// Kernel 2: per-channel SYRK pair = proj proj^T via bf16x3 tensor MMA.
// 128x128 tiles, upper-triangle + mirror. 256 threads (2M x 4N warps).
// ---------------------------------------------------------------------------
#define K2_SMEM 139264

__global__ __launch_bounds__(256) void k2_einsum()
{
    extern __shared__ char sm[];
    __nv_bfloat16* AH = (__nv_bfloat16*)sm;                  // [128][136]
    __nv_bfloat16* AL = (__nv_bfloat16*)(sm + 34816);
    __nv_bfloat16* BH = (__nv_bfloat16*)(sm + 69632);
    __nv_bfloat16* BL = (__nv_bfloat16*)(sm + 104448);

    int t = threadIdx.x, lane = t & 31, wid = t >> 5;
    int warpM = wid >> 2, warpN = wid & 3;
    int ch = blockIdx.y;

    // triangular tile map, n = 6
    int tt = blockIdx.x, bi = 0;
    while (tt >= 6 - bi) { tt -= 6 - bi; bi++; }
    int bj = bi + tt;
    int i0 = bi*128, j0 = bj*128;

    const __nv_bfloat16* Ph = g_projh + (size_t)ch*LL;
    const __nv_bfloat16* Pl = g_projl + (size_t)ch*LL;

    float c[16][4];
    #pragma unroll
    for (int i = 0; i < 16; i++) { c[i][0]=0.f; c[i][1]=0.f; c[i][2]=0.f; c[i][3]=0.f; }

    int grp = lane >> 3, lr = lane & 7;
    int a_row = (grp & 1)*8 + lr, a_k = (grp >> 1)*8;
    int b_row = (grp >> 1)*8 + lr, b_k = (grp & 1)*8;

    uint32_t ah_b = smaddr(AH), al_b = smaddr(AL);
    uint32_t bh_b = smaddr(BH), bl_b = smaddr(BL);

    for (int k0 = 0; k0 < LDIM; k0 += 128) {
        if (k0) __syncthreads();
        for (int i = t; i < 2048; i += 256) {
            int r = i >> 4, q = i & 15;
            ((float4*)(AH + r*X_STRIDE))[q] = ((const float4*)(Ph + (size_t)(i0+r)*LDIM + k0))[q];
            ((float4*)(AL + r*X_STRIDE))[q] = ((const float4*)(Pl + (size_t)(i0+r)*LDIM + k0))[q];
            ((float4*)(BH + r*X_STRIDE))[q] = ((const float4*)(Ph + (size_t)(j0+r)*LDIM + k0))[q];
            ((float4*)(BL + r*X_STRIDE))[q] = ((const float4*)(Pl + (size_t)(j0+r)*LDIM + k0))[q];
        }
        __syncthreads();

        for (int kb = 0; kb < 8; kb++) {
            uint32_t ah[4][4], al[4][4], bh[2][4], bl[2][4];
            #pragma unroll
            for (int mt = 0; mt < 4; mt++) {
                uint32_t off = (uint32_t)(((warpM*64 + mt*16 + a_row)*X_STRIDE + kb*16 + a_k)*2);
                ldsm4(ah[mt], ah_b + off);
                ldsm4(al[mt], al_b + off);
            }
            #pragma unroll
            for (int np = 0; np < 2; np++) {
                uint32_t off = (uint32_t)(((warpN*32 + np*16 + b_row)*X_STRIDE + kb*16 + b_k)*2);
                ldsm4(bh[np], bh_b + off);
                ldsm4(bl[np], bl_b + off);
            }
            #pragma unroll
            for (int mt = 0; mt < 4; mt++)
                #pragma unroll
                for (int nt = 0; nt < 4; nt++) {
                    int np = nt >> 1, h = (nt & 1)*2;
                    mma_bf16(c[mt*4+nt], ah[mt], bh[np][h], bh[np][h+1]);
                    mma_bf16(c[mt*4+nt], ah[mt], bl[np][h], bl[np][h+1]);
                    mma_bf16(c[mt*4+nt], al[mt], bh[np][h], bh[np][h+1]);
                }
        }
    }

    // ---- write C (and mirror for off-diagonal tiles) ----
    float* Cc = g_pair + (size_t)ch*LL;
    #pragma unroll
    for (int mt = 0; mt < 4; mt++) {
        int r = i0 + warpM*64 + mt*16 + (lane >> 2);
        #pragma unroll
        for (int nt = 0; nt < 4; nt++) {
            int col = j0 + warpN*32 + nt*8 + 2*(lane & 3);
            float2 v01 = make_float2(c[mt*4+nt][0], c[mt*4+nt][1]);
            float2 v23 = make_float2(c[mt*4+nt][2], c[mt*4+nt][3]);
            *(float2*)(Cc + (size_t)r*LDIM + col)     = v01;
            *(float2*)(Cc + (size_t)(r+8)*LDIM + col) = v23;
            if (bi != bj) {
                Cc[(size_t)col*LDIM     + r]   = v01.x;
                Cc[(size_t)(col+1)*LDIM + r]   = v01.y;
                Cc[(size_t)col*LDIM     + r+8] = v23.x;
                Cc[(size_t)(col+1)*LDIM + r+8] = v23.y;
            }
        }
    }
}

// ---------------------------------------------------------------------------
// Kernel 3: out = (layernorm_P(pair) @ oW^T + ob) * gate   (gate fp16)
// ---------------------------------------------------------------------------
__global__ __launch_bounds__(256) void k_out(
    const float* __restrict__ onw, const float* __restrict__ onb,
    const float* __restrict__ oW, const float* __restrict__ ob,
    float* __restrict__ out)
{
    __shared__ float sp[32][64];

    int t  = threadIdx.x;
    int i  = blockIdx.y;
    int j0 = blockIdx.x * 64;
    size_t posbase = (size_t)i*LDIM + j0;

    for (int idx = t; idx < 2048; idx += 256) {
        int cc = idx >> 6, jj = idx & 63;
        sp[cc][jj] = g_pair[(size_t)cc*LL + posbase + jj];
    }
    __syncthreads();

    if (t < 64) {
        float y[32];
        float sum = 0.0f, sq = 0.0f;
        #pragma unroll
        for (int cc = 0; cc < 32; cc++) {
            y[cc] = sp[cc][t];
            sum += y[cc];
            sq  += y[cc]*y[cc];
        }
        float mu   = sum * (1.0f/32.0f);
        float var  = sq  * (1.0f/32.0f) - mu*mu;
        float rstd = rsqrtf(var + 1e-5f);
        #pragma unroll
        for (int cc = 0; cc < 32; cc++)
            sp[cc][t] = (y[cc]-mu)*rstd*onw[cc] + onb[cc];
    }
    __syncthreads();

    int f = t & 127, jgrp = t >> 7;
    float wreg[32];
    const float4* ow4 = (const float4*)(oW + f*32);
    #pragma unroll
    for (int q = 0; q < 8; q++) {
        float4 v = ow4[q];
        wreg[q*4+0] = v.x; wreg[q*4+1] = v.y; wreg[q*4+2] = v.z; wreg[q*4+3] = v.w;
    }
    float obv = ob[f];

    for (int jb = 0; jb < 8; jb++) {
        int jj0 = jgrp*32 + jb*4;
        float a0 = obv, a1 = obv, a2 = obv, a3 = obv;
        #pragma unroll
        for (int cc = 0; cc < 32; cc++) {
            float4 y = *((const float4*)&sp[cc][jj0]);
            a0 += y.x*wreg[cc];
            a1 += y.y*wreg[cc];
            a2 += y.z*wreg[cc];
            a3 += y.w*wreg[cc];
        }
        size_t o = (posbase + jj0)*FDIM + f;
        a0 *= __half2float(g_gate16[o      ]);
        a1 *= __half2float(g_gate16[o + 128]);
        a2 *= __half2float(g_gate16[o + 256]);
        a3 *= __half2float(g_gate16[o + 384]);
        out[o      ] = a0;
        out[o + 128] = a1;
        out[o + 256] = a2;
        out[o + 384] = a3;
    }
}

// ---------------------------------------------------------------------------
extern "C" void kernel_launch(void* const* d_in, const int* in_sizes, int n_in,
                              void* d_out, int out_size)
{
    const float* feat = (const float*)d_in[0];
    const float* nw   = (const float*)d_in[1];
    const float* nb   = (const float*)d_in[2];
    const float* onw  = (const float*)d_in[3];
    const float* onb  = (const float*)d_in[4];
    const float* aW   = (const float*)d_in[5];
    const float* ab   = (const float*)d_in[6];
    const float* agW  = (const float*)d_in[7];
    const float* agb  = (const float*)d_in[8];
    const float* oW   = (const float*)d_in[9];
    const float* ob   = (const float*)d_in[10];
    const float* gW   = (const float*)d_in[11];
    const float* gb   = (const float*)d_in[12];
    float* out = (float*)d_out;

    cudaFuncSetAttribute(k1_ln_proj_gate, cudaFuncAttributeMaxDynamicSharedMemorySize, K1_SMEM);
    cudaFuncSetAttribute(k2_einsum,       cudaFuncAttributeMaxDynamicSharedMemorySize, K2_SMEM);

    k_pack<<<96, 256>>>(aW, agW, gW);
    k1_ln_proj_gate<<<LL/128, 256, K1_SMEM>>>(feat, nw, nb, ab, agb, gb);
    k2_einsum<<<dim3(21, 32), 256, K2_SMEM>>>();
    k_out<<<dim3(12, 768), 256>>>(onw, onb, oW, ob, out);
}